// round 7
// baseline (speedup 1.0000x reference)
#include <cuda_runtime.h>

#define D        32000
#define NV4      (D / 4)
#define THREADS  512
#define NWARP    (THREADS / 32)
#define CCAP     4096
#define LBUF     16

__device__ __forceinline__ float warpSum(float v) {
#pragma unroll
    for (int o = 16; o > 0; o >>= 1) v += __shfl_down_sync(0xffffffffu, v, o);
    return v;
}
__device__ __forceinline__ float warpMax(float v) {
#pragma unroll
    for (int o = 16; o > 0; o >>= 1) v = fmaxf(v, __shfl_down_sync(0xffffffffu, v, o));
    return v;
}

struct Red {
    float red[NWARP][4];
    float bcast[4];
    int   warpTot[NWARP];
    int   warpBase[NWARP];
    int   cnt;
    int   ovf;
};

// Block-reduce 4 partial sums; results broadcast via r->bcast[0..3].
__device__ void reduce4(float s0, float s1, float s2, float s3,
                        Red* r, int lane, int wid) {
    s0 = warpSum(s0); s1 = warpSum(s1); s2 = warpSum(s2); s3 = warpSum(s3);
    if (lane == 0) {
        r->red[wid][0] = s0; r->red[wid][1] = s1;
        r->red[wid][2] = s2; r->red[wid][3] = s3;
    }
    __syncthreads();
    if (wid == 0) {
        float a = (lane < NWARP) ? r->red[lane][0] : 0.f;
        float b = (lane < NWARP) ? r->red[lane][1] : 0.f;
        float c = (lane < NWARP) ? r->red[lane][2] : 0.f;
        float d = (lane < NWARP) ? r->red[lane][3] : 0.f;
        a = warpSum(a); b = warpSum(b); c = warpSum(c); d = warpSum(d);
        if (lane == 0) {
            r->bcast[0] = a; r->bcast[1] = b; r->bcast[2] = c; r->bcast[3] = d;
        }
    }
    __syncthreads();
}

// Block max of one float, broadcast via r->bcast[0].
__device__ void reduceMax(float m, Red* r, int lane, int wid) {
    m = warpMax(m);
    if (lane == 0) r->red[wid][0] = m;
    __syncthreads();
    if (wid == 0) {
        float t = (lane < NWARP) ? r->red[lane][0] : __int_as_float(0xff800000);
        t = warpMax(t);
        if (lane == 0) r->bcast[0] = t;
    }
    __syncthreads();
}

__device__ __forceinline__ void update_tau(float& tau_lo, float& tau_hi,
                                           float width, const Red* r) {
    // j_best = largest j in 1..4 with mass >= 1 (reference semantics)
    int jb = 0;
    if (r->bcast[0] >= 1.0f) jb = 1;
    if (r->bcast[1] >= 1.0f) jb = 2;
    if (r->bcast[2] >= 1.0f) jb = 3;
    if (r->bcast[3] >= 1.0f) jb = 4;
    tau_lo = tau_lo + (float)jb * width;
    tau_hi = tau_lo + width;
}

__global__ __launch_bounds__(THREADS, 3)
void entmax_kernel(const float* __restrict__ X, float* __restrict__ Y) {
    __shared__ float cvals[CCAP];
    __shared__ int   cidx[CCAP];
    __shared__ Red   r;

    const int tid  = threadIdx.x;
    const int lane = tid & 31;
    const int wid  = tid >> 5;
    const size_t rowoff = (size_t)blockIdx.x * D;
    const float4* __restrict__ xin4  = (const float4*)(X + rowoff);
    float4* __restrict__       yout4 = (float4*)(Y + rowoff);

    // ---- Phase 0: cheap sample max over the first 8192 elements (one float4
    //      per thread). sampleMax <= trueMax, so thr2 = sampleMax - 2 is a
    //      CONSERVATIVE active threshold: {x > trueMax-2} ⊆ {x > thr2}.
    if (tid == 0) { r.cnt = 0; r.ovf = 0; }
    float smax;
    {
        float4 v = xin4[tid];          // NV4 = 8000 > THREADS, always in-bounds
        smax = fmaxf(fmaxf(v.x, v.y), fmaxf(v.z, v.w));
    }
    reduceMax(smax, &r, lane, wid);
    const float thr2 = r.bcast[0] - 2.0f;   // raw-x units
    __syncthreads();   // protect r.red reuse below

    // ---- Phase 1 (single streaming pass): zero-fill Y, true row max, and
    //      buffered compaction of the conservative active superset.
    //      Extras (thr2 < 0.5x <= final tau_lo) contribute 0 to every probe
    //      mass, the normalizer, and write 0 in the scatter — harmless.
    float lmax = __int_as_float(0xff800000);  // -inf
    float lv[LBUF];
    int   li[LBUF];
    int   myCnt = 0;
    const float4 z4 = make_float4(0.f, 0.f, 0.f, 0.f);
    for (int k = tid; k < NV4; k += THREADS) {
        float4 v = __ldcs(&xin4[k]);
        __stcs(&yout4[k], z4);
        float m4 = fmaxf(fmaxf(v.x, v.y), fmaxf(v.z, v.w));
        lmax = fmaxf(lmax, m4);
        if (m4 > thr2) {
            int k4 = 4 * k;
            if (v.x > thr2) { if (myCnt < LBUF) { lv[myCnt] = 0.5f * v.x; li[myCnt] = k4 + 0; myCnt++; } else r.ovf = 1; }
            if (v.y > thr2) { if (myCnt < LBUF) { lv[myCnt] = 0.5f * v.y; li[myCnt] = k4 + 1; myCnt++; } else r.ovf = 1; }
            if (v.z > thr2) { if (myCnt < LBUF) { lv[myCnt] = 0.5f * v.z; li[myCnt] = k4 + 2; myCnt++; } else r.ovf = 1; }
            if (v.w > thr2) { if (myCnt < LBUF) { lv[myCnt] = 0.5f * v.w; li[myCnt] = k4 + 3; myCnt++; } else r.ovf = 1; }
        }
    }

    // ---- True row max -> tau bracket
    reduceMax(lmax, &r, lane, wid);
    const float mx = 0.5f * r.bcast[0];
    float tau_lo = mx - 1.0f;
    float tau_hi = mx - 0.005590169943749474f;   // (1/32000)^(alpha-1)
    __syncthreads();

    // ---- One block-wide exclusive scan of per-thread counts.
    //      FULL-WARP participation in every __shfl (R5 deadlock lesson).
    {
        int inc = myCnt;
#pragma unroll
        for (int d = 1; d < 32; d <<= 1) {
            int n = __shfl_up_sync(0xffffffffu, inc, d);
            if (lane >= d) inc += n;
        }
        if (lane == 31) r.warpTot[wid] = inc;
        __syncthreads();
        if (wid == 0) {
            int v = (lane < NWARP) ? r.warpTot[lane] : 0;
            int s = v;
#pragma unroll
            for (int d = 1; d < 32; d <<= 1) {
                int n = __shfl_up_sync(0xffffffffu, s, d);
                if (lane >= d) s += n;
            }
            if (lane < NWARP) r.warpBase[lane] = s - v;
            if (lane == NWARP - 1) r.cnt = s;
        }
        __syncthreads();
        int base = r.warpBase[wid] + inc - myCnt;
        for (int i = 0; i < myCnt; i++) {
            int p = base + i;
            if (p < CCAP) { cvals[p] = lv[i]; cidx[p] = li[i]; }
        }
    }
    __syncthreads();
    const int cnt = r.cnt;

    if (cnt <= CCAP && !r.ovf) {
        // ---- All 5 bisection iterations on the compact set
        for (int it = 0; it < 5; it++) {
            float width = (tau_hi - tau_lo) / 5.0f;
            const float t1 = tau_lo + 1.0f * width;
            const float t2 = tau_lo + 2.0f * width;
            const float t3 = tau_lo + 3.0f * width;
            const float t4 = tau_lo + 4.0f * width;
            float s0 = 0.f, s1 = 0.f, s2 = 0.f, s3 = 0.f;
            for (int k = tid; k < cnt; k += THREADS) {
                float c = cvals[k];
                float d0 = fmaxf(c - t1, 0.f); s0 = fmaf(d0, d0, s0);
                float d1 = fmaxf(c - t2, 0.f); s1 = fmaf(d1, d1, s1);
                float d2 = fmaxf(c - t3, 0.f); s2 = fmaf(d2, d2, s2);
                float d3 = fmaxf(c - t4, 0.f); s3 = fmaf(d3, d3, s3);
            }
            reduce4(s0, s1, s2, s3, &r, lane, wid);
            update_tau(tau_lo, tau_hi, width, &r);
        }
        // ---- Normalizer from the compact set
        float s = 0.f;
        for (int k = tid; k < cnt; k += THREADS) {
            float d0 = fmaxf(cvals[k] - tau_lo, 0.f);
            s = fmaf(d0, d0, s);
        }
        reduce4(s, 0.f, 0.f, 0.f, &r, lane, wid);
        const float invS = 1.0f / r.bcast[0];
        const float tau  = tau_lo;

        // ---- Scatter nonzeros (Y already zero-filled in phase 1; the
        //      reduce4 __syncthreads ordered those CTA-local stores).
        //      Inactive extras write 0.0 over 0.0 — harmless.
        float* __restrict__ yrow = (float*)(Y + rowoff);
        for (int k = tid; k < cnt; k += THREADS) {
            float d0 = fmaxf(cvals[k] - tau, 0.f);
            yrow[cidx[k]] = d0 * d0 * invS;
        }
    } else {
        // ---- Fallback (buffer overflow): full-row global passes, unconditional correctness
        for (int it = 0; it < 5; it++) {
            float width = (tau_hi - tau_lo) / 5.0f;
            const float t1 = tau_lo + 1.0f * width;
            const float t2 = tau_lo + 2.0f * width;
            const float t3 = tau_lo + 3.0f * width;
            const float t4 = tau_lo + 4.0f * width;
            float s0 = 0.f, s1 = 0.f, s2 = 0.f, s3 = 0.f;
            for (int k = tid; k < NV4; k += THREADS) {
                float4 v = xin4[k];
#define ACC(c)                                                        \
                {                                                     \
                    float cs = 0.5f * (c);                            \
                    float d0 = fmaxf(cs - t1, 0.f); s0 = fmaf(d0, d0, s0); \
                    float d1 = fmaxf(cs - t2, 0.f); s1 = fmaf(d1, d1, s1); \
                    float d2 = fmaxf(cs - t3, 0.f); s2 = fmaf(d2, d2, s2); \
                    float d3 = fmaxf(cs - t4, 0.f); s3 = fmaf(d3, d3, s3); \
                }
                ACC(v.x) ACC(v.y) ACC(v.z) ACC(v.w)
#undef ACC
            }
            reduce4(s0, s1, s2, s3, &r, lane, wid);
            update_tau(tau_lo, tau_hi, width, &r);
        }
        float s = 0.f;
        for (int k = tid; k < NV4; k += THREADS) {
            float4 v = xin4[k];
            float d0 = fmaxf(0.5f * v.x - tau_lo, 0.f); s = fmaf(d0, d0, s);
            float d1 = fmaxf(0.5f * v.y - tau_lo, 0.f); s = fmaf(d1, d1, s);
            float d2 = fmaxf(0.5f * v.z - tau_lo, 0.f); s = fmaf(d2, d2, s);
            float d3 = fmaxf(0.5f * v.w - tau_lo, 0.f); s = fmaf(d3, d3, s);
        }
        reduce4(s, 0.f, 0.f, 0.f, &r, lane, wid);
        const float invS = 1.0f / r.bcast[0];
        const float tau  = tau_lo;
        for (int k = tid; k < NV4; k += THREADS) {
            float4 v = xin4[k];
            float4 o;
            float d0 = fmaxf(0.5f * v.x - tau, 0.f); o.x = d0 * d0 * invS;
            float d1 = fmaxf(0.5f * v.y - tau, 0.f); o.y = d1 * d1 * invS;
            float d2 = fmaxf(0.5f * v.z - tau, 0.f); o.z = d2 * d2 * invS;
            float d3 = fmaxf(0.5f * v.w - tau, 0.f); o.w = d3 * d3 * invS;
            yout4[k] = o;
        }
    }
}

extern "C" void kernel_launch(void* const* d_in, const int* in_sizes, int n_in,
                              void* d_out, int out_size) {
    const float* X = (const float*)d_in[0];
    float* Y = (float*)d_out;
    const int rows = in_sizes[0] / D;   // 8192 for (4, 2048, 32000)
    entmax_kernel<<<rows, THREADS>>>(X, Y);
}

// round 8
// speedup vs baseline: 1.6196x; 1.6196x over previous
#include <cuda_runtime.h>

#define D        32000
#define NV4      (D / 4)
#define THREADS  512
#define NWARP    (THREADS / 32)
#define CCAP     4096

__device__ __forceinline__ float warpSum(float v) {
#pragma unroll
    for (int o = 16; o > 0; o >>= 1) v += __shfl_down_sync(0xffffffffu, v, o);
    return v;
}
__device__ __forceinline__ float warpMax(float v) {
#pragma unroll
    for (int o = 16; o > 0; o >>= 1) v = fmaxf(v, __shfl_down_sync(0xffffffffu, v, o));
    return v;
}

struct Red {
    float red[NWARP][4];
    float bcast[4];
    int   cnt;
};

// Block-reduce 4 partial sums; results broadcast via r->bcast[0..3].
__device__ void reduce4(float s0, float s1, float s2, float s3,
                        Red* r, int lane, int wid) {
    s0 = warpSum(s0); s1 = warpSum(s1); s2 = warpSum(s2); s3 = warpSum(s3);
    if (lane == 0) {
        r->red[wid][0] = s0; r->red[wid][1] = s1;
        r->red[wid][2] = s2; r->red[wid][3] = s3;
    }
    __syncthreads();
    if (wid == 0) {
        float a = (lane < NWARP) ? r->red[lane][0] : 0.f;
        float b = (lane < NWARP) ? r->red[lane][1] : 0.f;
        float c = (lane < NWARP) ? r->red[lane][2] : 0.f;
        float d = (lane < NWARP) ? r->red[lane][3] : 0.f;
        a = warpSum(a); b = warpSum(b); c = warpSum(c); d = warpSum(d);
        if (lane == 0) {
            r->bcast[0] = a; r->bcast[1] = b; r->bcast[2] = c; r->bcast[3] = d;
        }
    }
    __syncthreads();
}

__device__ __forceinline__ void update_tau(float& tau_lo, float& tau_hi,
                                           float width, const Red* r) {
    // j_best = largest j in 1..4 with mass >= 1 (reference semantics)
    int jb = 0;
    if (r->bcast[0] >= 1.0f) jb = 1;
    if (r->bcast[1] >= 1.0f) jb = 2;
    if (r->bcast[2] >= 1.0f) jb = 3;
    if (r->bcast[3] >= 1.0f) jb = 4;
    tau_lo = tau_lo + (float)jb * width;
    tau_hi = tau_lo + width;
}

__global__ __launch_bounds__(THREADS, 3)
void entmax_kernel(const float* __restrict__ X, float* __restrict__ Y) {
    __shared__ float cvals[CCAP];
    __shared__ int   cidx[CCAP];
    __shared__ Red   r;

    const int tid  = threadIdx.x;
    const int lane = tid & 31;
    const int wid  = tid >> 5;
    const size_t rowoff = (size_t)blockIdx.x * D;
    const float4* __restrict__ xin4  = (const float4*)(X + rowoff);
    float4* __restrict__       yout4 = (float4*)(Y + rowoff);

    // ---- Pass 1: stream row from HBM (pure reads), row max.
    //      max(0.5x) = 0.5*max(x), so track the raw max.
    float lmax = __int_as_float(0xff800000);  // -inf
    for (int k = tid; k < NV4; k += THREADS) {
        float4 v = xin4[k];
        lmax = fmaxf(lmax, fmaxf(fmaxf(v.x, v.y), fmaxf(v.z, v.w)));
    }
    lmax = warpMax(lmax);
    if (lane == 0) r.red[wid][0] = lmax;
    if (tid == 0) r.cnt = 0;
    __syncthreads();
    if (wid == 0) {
        float m = (lane < NWARP) ? r.red[lane][0] : __int_as_float(0xff800000);
        m = warpMax(m);
        if (lane == 0) r.bcast[0] = m;
    }
    __syncthreads();
    const float mx = 0.5f * r.bcast[0];

    float tau_lo = mx - 1.0f;
    float tau_hi = mx - 0.005590169943749474f;   // (1/32000)^(alpha-1)

    // ---- Pass 2 (reads L2-hot, writes pure DRAM): zero-fill Y and compact
    //      actives {0.5x > tau_lo} directly to SMEM via guarded atomics.
    //      Everything below tau_lo contributes 0 to all probe masses, the
    //      normalizer, and the output (tau never decreases below tau_lo).
    //      The atomic executes only on ~2% of float4s (~570 ops/row total).
    const float thr2 = 2.0f * tau_lo;   // compare in raw-x units
    const float4 z4 = make_float4(0.f, 0.f, 0.f, 0.f);
    for (int k = tid; k < NV4; k += THREADS) {
        float4 v = __ldcs(&xin4[k]);
        __stcs(&yout4[k], z4);
        float m4 = fmaxf(fmaxf(v.x, v.y), fmaxf(v.z, v.w));
        if (m4 > thr2) {
            int k4 = 4 * k;
            if (v.x > thr2) { int p = atomicAdd(&r.cnt, 1); if (p < CCAP) { cvals[p] = 0.5f * v.x; cidx[p] = k4 + 0; } }
            if (v.y > thr2) { int p = atomicAdd(&r.cnt, 1); if (p < CCAP) { cvals[p] = 0.5f * v.y; cidx[p] = k4 + 1; } }
            if (v.z > thr2) { int p = atomicAdd(&r.cnt, 1); if (p < CCAP) { cvals[p] = 0.5f * v.z; cidx[p] = k4 + 2; } }
            if (v.w > thr2) { int p = atomicAdd(&r.cnt, 1); if (p < CCAP) { cvals[p] = 0.5f * v.w; cidx[p] = k4 + 3; } }
        }
    }
    __syncthreads();
    const int cnt = r.cnt;

    if (cnt <= CCAP) {
        // ---- All 5 bisection iterations on the tiny compact set
        for (int it = 0; it < 5; it++) {
            float width = (tau_hi - tau_lo) / 5.0f;
            const float t1 = tau_lo + 1.0f * width;
            const float t2 = tau_lo + 2.0f * width;
            const float t3 = tau_lo + 3.0f * width;
            const float t4 = tau_lo + 4.0f * width;
            float s0 = 0.f, s1 = 0.f, s2 = 0.f, s3 = 0.f;
            for (int k = tid; k < cnt; k += THREADS) {
                float c = cvals[k];
                float d0 = fmaxf(c - t1, 0.f); s0 = fmaf(d0, d0, s0);
                float d1 = fmaxf(c - t2, 0.f); s1 = fmaf(d1, d1, s1);
                float d2 = fmaxf(c - t3, 0.f); s2 = fmaf(d2, d2, s2);
                float d3 = fmaxf(c - t4, 0.f); s3 = fmaf(d3, d3, s3);
            }
            reduce4(s0, s1, s2, s3, &r, lane, wid);
            update_tau(tau_lo, tau_hi, width, &r);
        }
        // ---- Normalizer from the compact set
        float s = 0.f;
        for (int k = tid; k < cnt; k += THREADS) {
            float d0 = fmaxf(cvals[k] - tau_lo, 0.f);
            s = fmaf(d0, d0, s);
        }
        reduce4(s, 0.f, 0.f, 0.f, &r, lane, wid);
        const float invS = 1.0f / r.bcast[0];
        const float tau  = tau_lo;

        // ---- Scatter the few nonzeros (Y already zero-filled in pass 2;
        //      reduce4's __syncthreads ordered those CTA-local stores)
        float* __restrict__ yrow = (float*)(Y + rowoff);
        for (int k = tid; k < cnt; k += THREADS) {
            float d0 = fmaxf(cvals[k] - tau, 0.f);
            yrow[cidx[k]] = d0 * d0 * invS;
        }
    } else {
        // ---- Fallback (compact buffer overflow): full-row global passes
        for (int it = 0; it < 5; it++) {
            float width = (tau_hi - tau_lo) / 5.0f;
            const float t1 = tau_lo + 1.0f * width;
            const float t2 = tau_lo + 2.0f * width;
            const float t3 = tau_lo + 3.0f * width;
            const float t4 = tau_lo + 4.0f * width;
            float s0 = 0.f, s1 = 0.f, s2 = 0.f, s3 = 0.f;
            for (int k = tid; k < NV4; k += THREADS) {
                float4 v = xin4[k];
#define ACC(c)                                                        \
                {                                                     \
                    float cs = 0.5f * (c);                            \
                    float d0 = fmaxf(cs - t1, 0.f); s0 = fmaf(d0, d0, s0); \
                    float d1 = fmaxf(cs - t2, 0.f); s1 = fmaf(d1, d1, s1); \
                    float d2 = fmaxf(cs - t3, 0.f); s2 = fmaf(d2, d2, s2); \
                    float d3 = fmaxf(cs - t4, 0.f); s3 = fmaf(d3, d3, s3); \
                }
                ACC(v.x) ACC(v.y) ACC(v.z) ACC(v.w)
#undef ACC
            }
            reduce4(s0, s1, s2, s3, &r, lane, wid);
            update_tau(tau_lo, tau_hi, width, &r);
        }
        float s = 0.f;
        for (int k = tid; k < NV4; k += THREADS) {
            float4 v = xin4[k];
            float d0 = fmaxf(0.5f * v.x - tau_lo, 0.f); s = fmaf(d0, d0, s);
            float d1 = fmaxf(0.5f * v.y - tau_lo, 0.f); s = fmaf(d1, d1, s);
            float d2 = fmaxf(0.5f * v.z - tau_lo, 0.f); s = fmaf(d2, d2, s);
            float d3 = fmaxf(0.5f * v.w - tau_lo, 0.f); s = fmaf(d3, d3, s);
        }
        reduce4(s, 0.f, 0.f, 0.f, &r, lane, wid);
        const float invS = 1.0f / r.bcast[0];
        const float tau  = tau_lo;
        for (int k = tid; k < NV4; k += THREADS) {
            float4 v = xin4[k];
            float4 o;
            float d0 = fmaxf(0.5f * v.x - tau, 0.f); o.x = d0 * d0 * invS;
            float d1 = fmaxf(0.5f * v.y - tau, 0.f); o.y = d1 * d1 * invS;
            float d2 = fmaxf(0.5f * v.z - tau, 0.f); o.z = d2 * d2 * invS;
            float d3 = fmaxf(0.5f * v.w - tau, 0.f); o.w = d3 * d3 * invS;
            yout4[k] = o;
        }
    }
}

extern "C" void kernel_launch(void* const* d_in, const int* in_sizes, int n_in,
                              void* d_out, int out_size) {
    const float* X = (const float*)d_in[0];
    float* Y = (float*)d_out;
    const int rows = in_sizes[0] / D;   // 8192 for (4, 2048, 32000)
    entmax_kernel<<<rows, THREADS>>>(X, Y);
}

// round 9
// speedup vs baseline: 1.7171x; 1.0602x over previous
#include <cuda_runtime.h>

#define D        32000
#define NV4      (D / 4)          // 8000
#define THREADS  512
#define NWARP    (THREADS / 32)
#define MAIN_ITERS 15             // 15*512 = 7680
#define TAILV4   (NV4 - MAIN_ITERS * THREADS)   // 320
#define CCAP     3072

__device__ __forceinline__ float warpSum(float v) {
#pragma unroll
    for (int o = 16; o > 0; o >>= 1) v += __shfl_down_sync(0xffffffffu, v, o);
    return v;
}
__device__ __forceinline__ float warpMax(float v) {
#pragma unroll
    for (int o = 16; o > 0; o >>= 1) v = fmaxf(v, __shfl_down_sync(0xffffffffu, v, o));
    return v;
}

struct Red {
    float red[NWARP][4];
    float bcast[4];
    int   cnt;
};

// Block-reduce 4 partial sums; results broadcast via r->bcast[0..3].
__device__ void reduce4(float s0, float s1, float s2, float s3,
                        Red* r, int lane, int wid) {
    s0 = warpSum(s0); s1 = warpSum(s1); s2 = warpSum(s2); s3 = warpSum(s3);
    if (lane == 0) {
        r->red[wid][0] = s0; r->red[wid][1] = s1;
        r->red[wid][2] = s2; r->red[wid][3] = s3;
    }
    __syncthreads();
    if (wid == 0) {
        float a = (lane < NWARP) ? r->red[lane][0] : 0.f;
        float b = (lane < NWARP) ? r->red[lane][1] : 0.f;
        float c = (lane < NWARP) ? r->red[lane][2] : 0.f;
        float d = (lane < NWARP) ? r->red[lane][3] : 0.f;
        a = warpSum(a); b = warpSum(b); c = warpSum(c); d = warpSum(d);
        if (lane == 0) {
            r->bcast[0] = a; r->bcast[1] = b; r->bcast[2] = c; r->bcast[3] = d;
        }
    }
    __syncthreads();
}

__device__ __forceinline__ void update_tau(float& tau_lo, float& tau_hi,
                                           float width, const Red* r) {
    // j_best = largest j in 1..4 with mass >= 1 (reference semantics)
    int jb = 0;
    if (r->bcast[0] >= 1.0f) jb = 1;
    if (r->bcast[1] >= 1.0f) jb = 2;
    if (r->bcast[2] >= 1.0f) jb = 3;
    if (r->bcast[3] >= 1.0f) jb = 4;
    tau_lo = tau_lo + (float)jb * width;
    tau_hi = tau_lo + width;
}

__global__ __launch_bounds__(THREADS, 4)
void entmax_kernel(const float* __restrict__ X, float* __restrict__ Y) {
    __shared__ float cvals[CCAP];
    __shared__ int   cidx[CCAP];
    __shared__ Red   r;

    const int tid  = threadIdx.x;
    const int lane = tid & 31;
    const int wid  = tid >> 5;
    const size_t rowoff = (size_t)blockIdx.x * D;
    const float4* __restrict__ xin4  = (const float4*)(X + rowoff);
    float4* __restrict__       yout4 = (float4*)(Y + rowoff);

    // ---- Pass 1: stream row from HBM (pure reads), row max.
    //      Compile-time trip count (15) + tail so ptxas can batch LDGs (MLP).
    float lmax = __int_as_float(0xff800000);  // -inf
#pragma unroll
    for (int i = 0; i < MAIN_ITERS; i++) {
        float4 v = xin4[tid + i * THREADS];
        lmax = fmaxf(lmax, fmaxf(fmaxf(v.x, v.y), fmaxf(v.z, v.w)));
    }
    if (tid < TAILV4) {
        float4 v = xin4[MAIN_ITERS * THREADS + tid];
        lmax = fmaxf(lmax, fmaxf(fmaxf(v.x, v.y), fmaxf(v.z, v.w)));
    }
    lmax = warpMax(lmax);
    if (lane == 0) r.red[wid][0] = lmax;
    if (tid == 0) r.cnt = 0;
    __syncthreads();
    if (wid == 0) {
        float m = (lane < NWARP) ? r.red[lane][0] : __int_as_float(0xff800000);
        m = warpMax(m);
        if (lane == 0) r.bcast[0] = m;
    }
    __syncthreads();
    const float mx = 0.5f * r.bcast[0];

    float tau_lo = mx - 1.0f;
    float tau_hi = mx - 0.005590169943749474f;   // (1/32000)^(alpha-1)

    // ---- Pass 2 (reads L2-hot, writes pure DRAM): zero-fill Y and compact
    //      actives {0.5x > tau_lo} to SMEM via guarded atomics (~2% taken).
    const float thr2 = 2.0f * tau_lo;   // raw-x units
    const float4 z4 = make_float4(0.f, 0.f, 0.f, 0.f);
#pragma unroll 5
    for (int i = 0; i < MAIN_ITERS; i++) {
        int k = tid + i * THREADS;
        float4 v = __ldcs(&xin4[k]);
        __stcs(&yout4[k], z4);
        float m4 = fmaxf(fmaxf(v.x, v.y), fmaxf(v.z, v.w));
        if (m4 > thr2) {
            int k4 = 4 * k;
            if (v.x > thr2) { int p = atomicAdd(&r.cnt, 1); if (p < CCAP) { cvals[p] = 0.5f * v.x; cidx[p] = k4 + 0; } }
            if (v.y > thr2) { int p = atomicAdd(&r.cnt, 1); if (p < CCAP) { cvals[p] = 0.5f * v.y; cidx[p] = k4 + 1; } }
            if (v.z > thr2) { int p = atomicAdd(&r.cnt, 1); if (p < CCAP) { cvals[p] = 0.5f * v.z; cidx[p] = k4 + 2; } }
            if (v.w > thr2) { int p = atomicAdd(&r.cnt, 1); if (p < CCAP) { cvals[p] = 0.5f * v.w; cidx[p] = k4 + 3; } }
        }
    }
    if (tid < TAILV4) {
        int k = MAIN_ITERS * THREADS + tid;
        float4 v = __ldcs(&xin4[k]);
        __stcs(&yout4[k], z4);
        float m4 = fmaxf(fmaxf(v.x, v.y), fmaxf(v.z, v.w));
        if (m4 > thr2) {
            int k4 = 4 * k;
            if (v.x > thr2) { int p = atomicAdd(&r.cnt, 1); if (p < CCAP) { cvals[p] = 0.5f * v.x; cidx[p] = k4 + 0; } }
            if (v.y > thr2) { int p = atomicAdd(&r.cnt, 1); if (p < CCAP) { cvals[p] = 0.5f * v.y; cidx[p] = k4 + 1; } }
            if (v.z > thr2) { int p = atomicAdd(&r.cnt, 1); if (p < CCAP) { cvals[p] = 0.5f * v.z; cidx[p] = k4 + 2; } }
            if (v.w > thr2) { int p = atomicAdd(&r.cnt, 1); if (p < CCAP) { cvals[p] = 0.5f * v.w; cidx[p] = k4 + 3; } }
        }
    }
    __syncthreads();
    const int cnt = r.cnt;

    if (cnt <= CCAP) {
        // ---- All 5 bisection iterations on the tiny compact set
        for (int it = 0; it < 5; it++) {
            float width = (tau_hi - tau_lo) / 5.0f;
            const float t1 = tau_lo + 1.0f * width;
            const float t2 = tau_lo + 2.0f * width;
            const float t3 = tau_lo + 3.0f * width;
            const float t4 = tau_lo + 4.0f * width;
            float s0 = 0.f, s1 = 0.f, s2 = 0.f, s3 = 0.f;
            for (int k = tid; k < cnt; k += THREADS) {
                float c = cvals[k];
                float d0 = fmaxf(c - t1, 0.f); s0 = fmaf(d0, d0, s0);
                float d1 = fmaxf(c - t2, 0.f); s1 = fmaf(d1, d1, s1);
                float d2 = fmaxf(c - t3, 0.f); s2 = fmaf(d2, d2, s2);
                float d3 = fmaxf(c - t4, 0.f); s3 = fmaf(d3, d3, s3);
            }
            reduce4(s0, s1, s2, s3, &r, lane, wid);
            update_tau(tau_lo, tau_hi, width, &r);
        }
        // ---- Normalizer from the compact set
        float s = 0.f;
        for (int k = tid; k < cnt; k += THREADS) {
            float d0 = fmaxf(cvals[k] - tau_lo, 0.f);
            s = fmaf(d0, d0, s);
        }
        reduce4(s, 0.f, 0.f, 0.f, &r, lane, wid);
        const float invS = 1.0f / r.bcast[0];
        const float tau  = tau_lo;

        // ---- Scatter the few nonzeros (Y already zero-filled in pass 2;
        //      reduce4's __syncthreads ordered those CTA-local stores)
        float* __restrict__ yrow = (float*)(Y + rowoff);
        for (int k = tid; k < cnt; k += THREADS) {
            float d0 = fmaxf(cvals[k] - tau, 0.f);
            yrow[cidx[k]] = d0 * d0 * invS;
        }
    } else {
        // ---- Fallback (compact buffer overflow): full-row global passes
        for (int it = 0; it < 5; it++) {
            float width = (tau_hi - tau_lo) / 5.0f;
            const float t1 = tau_lo + 1.0f * width;
            const float t2 = tau_lo + 2.0f * width;
            const float t3 = tau_lo + 3.0f * width;
            const float t4 = tau_lo + 4.0f * width;
            float s0 = 0.f, s1 = 0.f, s2 = 0.f, s3 = 0.f;
            for (int k = tid; k < NV4; k += THREADS) {
                float4 v = xin4[k];
#define ACC(c)                                                        \
                {                                                     \
                    float cs = 0.5f * (c);                            \
                    float d0 = fmaxf(cs - t1, 0.f); s0 = fmaf(d0, d0, s0); \
                    float d1 = fmaxf(cs - t2, 0.f); s1 = fmaf(d1, d1, s1); \
                    float d2 = fmaxf(cs - t3, 0.f); s2 = fmaf(d2, d2, s2); \
                    float d3 = fmaxf(cs - t4, 0.f); s3 = fmaf(d3, d3, s3); \
                }
                ACC(v.x) ACC(v.y) ACC(v.z) ACC(v.w)
#undef ACC
            }
            reduce4(s0, s1, s2, s3, &r, lane, wid);
            update_tau(tau_lo, tau_hi, width, &r);
        }
        float s = 0.f;
        for (int k = tid; k < NV4; k += THREADS) {
            float4 v = xin4[k];
            float d0 = fmaxf(0.5f * v.x - tau_lo, 0.f); s = fmaf(d0, d0, s);
            float d1 = fmaxf(0.5f * v.y - tau_lo, 0.f); s = fmaf(d1, d1, s);
            float d2 = fmaxf(0.5f * v.z - tau_lo, 0.f); s = fmaf(d2, d2, s);
            float d3 = fmaxf(0.5f * v.w - tau_lo, 0.f); s = fmaf(d3, d3, s);
        }
        reduce4(s, 0.f, 0.f, 0.f, &r, lane, wid);
        const float invS = 1.0f / r.bcast[0];
        const float tau  = tau_lo;
        for (int k = tid; k < NV4; k += THREADS) {
            float4 v = xin4[k];
            float4 o;
            float d0 = fmaxf(0.5f * v.x - tau, 0.f); o.x = d0 * d0 * invS;
            float d1 = fmaxf(0.5f * v.y - tau, 0.f); o.y = d1 * d1 * invS;
            float d2 = fmaxf(0.5f * v.z - tau, 0.f); o.z = d2 * d2 * invS;
            float d3 = fmaxf(0.5f * v.w - tau, 0.f); o.w = d3 * d3 * invS;
            yout4[k] = o;
        }
    }
}

extern "C" void kernel_launch(void* const* d_in, const int* in_sizes, int n_in,
                              void* d_out, int out_size) {
    const float* X = (const float*)d_in[0];
    float* Y = (float*)d_out;
    const int rows = in_sizes[0] / D;   // 8192 for (4, 2048, 32000)
    entmax_kernel<<<rows, THREADS>>>(X, Y);
}